// round 17
// baseline (speedup 1.0000x reference)
#include <cuda_runtime.h>
#include <cstdint>

// Problem shape (fixed by the dataset)
#define N_   64
#define T_   256
#define V_   4000
#define S_   32
#define L_   65           // 2*S+1
#define LP   66           // padded row stride -> aligned float2 loads in DP
#define LN2  0.6931471805599453f
#define WMASK 0xffffffffu
#define TILE_F   (T_ * LP)       // 16896 floats per sequence
#define TILE_F4  (TILE_F / 4)    // 4224 float4
#define NROW     (N_ * T_)       // 16384 rows
#define PG1      592             // k1 grid: 148 SMs x 4 CTAs (512 thr each)
#define NGRP     (PG1 * 4)       // 2368 independent row-groups

// Device scratch (no cudaMalloc allowed). g_done is reset by its consumer
// before kernel end -> identical state on every graph replay.
__device__ float g_p[(size_t)N_ * TILE_F];   // ext-label probs, stride 66
__device__ float g_nll[N_];
__device__ int   g_done;                     // DP completion count

__device__ __forceinline__ void cpa16(unsigned int smem_addr, const float4* gptr) {
    asm volatile("cp.async.cg.shared.global [%0], [%1], 16;"
                 :: "r"(smem_addr), "l"(gptr));
}
__device__ __forceinline__ void cpa_commit() {
    asm volatile("cp.async.commit_group;");
}
__device__ __forceinline__ void cpa_wait_all() {
    asm volatile("cp.async.wait_group 0;" ::: "memory");
}

// ---------------------------------------------------------------------------
// Kernel 1: softmax denominators + extended-label prob gather.
// Round-16 structure (four independent 128-thread groups per 512-thread CTA,
// one row per group, named-barrier group reduction). Change: iterations
// k=0..6 are unconditionally in range (tg+768 <= 895 < 1000); only the k=7
// tail (tg < 104) is guarded -> shorter predicate chains in the load burst.
// ---------------------------------------------------------------------------
__global__ void __launch_bounds__(512, 4)
k_softmax_gather(const float* __restrict__ y_pred,
                 const int*   __restrict__ y_target) {
    const int tid  = threadIdx.x;
    const int grp  = tid >> 7;            // group 0..3
    const int tg   = tid & 127;           // tid within group
    const int wg   = (tid >> 5) & 3;      // warp within group
    const int lane = tid & 31;

    __shared__ float part[4][2][4];       // [group][parity][warp-in-group]

    int par = 0;
    for (int r = blockIdx.x * 4 + grp; r < NROW; r += NGRP, par ^= 1) {
        const int n = r >> 8;             // T_ = 256
        const float*  row = y_pred + (size_t)r * V_;
        const float4* r4  = reinterpret_cast<const float4*>(row);

        float s = 0.0f;
        #pragma unroll
        for (int k = 0; k < 7; k++) {     // always in range: tg+768 <= 895
            float4 v = __ldcs(r4 + tg + k * 128);
            s += __expf(v.x) + __expf(v.y) + __expf(v.z) + __expf(v.w);
        }
        if (tg < (V_ / 4 - 896)) {        // tail: tg < 104
            float4 v = __ldcs(r4 + tg + 896);
            s += __expf(v.x) + __expf(v.y) + __expf(v.z) + __expf(v.w);
        }
        #pragma unroll
        for (int off = 16; off; off >>= 1)
            s += __shfl_xor_sync(WMASK, s, off);
        if (lane == 0) part[grp][par][wg] = s;

        // group-scoped barrier (ids 1..4; id 0 reserved for __syncthreads)
        asm volatile("bar.sync %0, 128;" :: "r"(grp + 1) : "memory");

        float S = part[grp][par][0] + part[grp][par][1]
                + part[grp][par][2] + part[grp][par][3];

        if (tg < L_) {                    // gather: row just read -> L1 hits
            int lab = (tg & 1) ? __ldg(y_target + n * S_ + (tg >> 1)) : 0;
            g_p[(size_t)r * LP + tg] = __fdividef(__expf(__ldg(row + lab)), S);
        }
    }
}

// ---------------------------------------------------------------------------
// Kernel 2: bidirectional CTC DP (round-16 math, unchanged) launched with
// PROGRAMMATIC DEPENDENT LAUNCH: the g_p-independent preamble (y_target
// loads, skip flags) runs while k1 drains; griddepcontrol.wait gates the
// g_p preload on k1's memory being visible.
// ---------------------------------------------------------------------------
__global__ void __launch_bounds__(128)
k_ctc_dp(const int* __restrict__ y_target, float* __restrict__ out) {
    extern __shared__ float p_s[];        // [T_ * LP] = 67,584 B
    __shared__ float bS[L_];              // backward beta_127
    __shared__ int   kB_sh;
    const int n    = blockIdx.x;
    const int tid  = threadIdx.x;
    const int wid  = tid >> 5;
    const int lane = tid & 31;

    // --- PDL preamble: independent of g_p ---
    int yl = __ldg(y_target + n * S_ + lane);    // y[lane] (per-warp copy)

    // wait for k1's writes to be visible, then preload the tile
    asm volatile("griddepcontrol.wait;" ::: "memory");
    {
        const float4* src = reinterpret_cast<const float4*>(g_p + (size_t)n * TILE_F);
        unsigned int dst = (unsigned int)__cvta_generic_to_shared(p_s);
        for (int i = tid; i < TILE_F4; i += 128)
            cpa16(dst + 16u * i, src + i);
        cpa_commit();
        cpa_wait_all();
    }
    __syncthreads();
    if (wid >= 2) return;                 // warps 2,3 done after preload

    float b, c, f;                        // fwd: alpha(2l), alpha(2l+1), alpha(64)
    int   kF = 0;

    if (wid == 0) {
        // ------------------------- FORWARD (127 steps) -------------------------
        int ylm = __shfl_up_sync(WMASK, yl, 1);
        const float skF = ((lane >= 1) && (yl != ylm)) ? 1.0f : 0.0f;

        b = 0.f; c = 0.f; f = 0.f;
        if (lane == 0) { b = p_s[0]; c = p_s[1]; }       // alpha at t=0

        float2 pq = *reinterpret_cast<const float2*>(p_s + LP + 2 * lane);
        float  p64 = p_s[LP + 64];

        #pragma unroll 4
        for (int t = 1; t <= 127; t++) {
            int tn = (t < 127) ? t + 1 : 127;
            const float* nb = p_s + tn * LP;
            float2 nq = *reinterpret_cast<const float2*>(nb + 2 * lane);
            float  n64 = nb[64];

            float cu = __shfl_up_sync(WMASK, c, 1);
            cu = (lane >= 1) ? cu : 0.f;
            float fn = (f + c) * p64;                     // state 64 uses OLD c
            float bn = fmaf(cu, pq.x, b * pq.x);          // state 2l (blank)
            float cn = fmaf(cu * skF, pq.y, (c + b) * pq.y); // state 2l+1
            b = bn; c = cn; f = fn;
            if ((t & 3) == 0) {                           // exact pow2 rescale
                float m = fmaxf(b, c);
                if (lane == 31) m = fmaxf(m, f);
                int mi = __reduce_max_sync(WMASK, __float_as_int(m));
                int e  = mi >> 23;
                float sc = __int_as_float((254 - e) << 23);   // 2^(127-e)
                b *= sc; c *= sc; f *= sc;
                kF += 127 - e;
            }
            pq = nq; p64 = n64;
        }
        // FINAL rescale: max(alpha_127) into [1,2) -> combine cannot underflow
        {
            float m = fmaxf(b, c);
            if (lane == 31) m = fmaxf(m, f);
            int mi = __reduce_max_sync(WMASK, __float_as_int(m));
            int e  = mi >> 23;
            float sc = __int_as_float((254 - e) << 23);
            b *= sc; c *= sc; f *= sc;
            kF += 127 - e;
        }
    } else {
        // ------------------------- BACKWARD (128 steps) ------------------------
        int ylp = __shfl_down_sync(WMASK, yl, 1);
        const float skB = ((lane <= 30) && (ylp != yl)) ? 1.0f : 0.0f;

        float B = 0.f, C = 0.f, F = 0.f;
        int   kB = 0;
        if (lane == 31) { C = 1.f; F = 1.f; }           // beta_255(63)=beta_255(64)=1

        float2 qq = *reinterpret_cast<const float2*>(p_s + 255 * LP + 2 * lane);
        float  q64 = p_s[255 * LP + 64];

        #pragma unroll 4
        for (int i = 0; i < 128; i++) {                 // beta_254..beta_127
            int qn = (i < 127) ? 254 - i : 128;
            const float* nb = p_s + qn * LP;
            float2 nq = *reinterpret_cast<const float2*>(nb + 2 * lane);
            float  n64 = nb[64];

            float u = qq.x * B;                         // q(2l)  * beta(2l)
            float v = qq.y * C;                         // q(2l+1)* beta(2l+1)
            float wd = __shfl_down_sync(WMASK, u, 1);   // q(2l+2)*beta(2l+2)
            float x  = __shfl_down_sync(WMASK, v, 1);   // q(2l+3)*beta(2l+3)
            float Fq = q64 * F;
            if (lane == 31) wd = Fq;                    // beta(63): q(64)*beta(64)
            float Bn = u + v;
            float Cn = fmaf(skB, x, v + wd);
            B = Bn; C = Cn; F = Fq;
            if ((i & 3) == 3) {                         // rescale (incl. final i=127)
                float m = fmaxf(B, C);
                if (lane == 31) m = fmaxf(m, F);
                int mi = __reduce_max_sync(WMASK, __float_as_int(m));
                int e  = mi >> 23;
                float sc = __int_as_float((254 - e) << 23);
                B *= sc; C *= sc; F *= sc;
                kB += 127 - e;
            }
            qq = nq; q64 = n64;
        }

        bS[2 * lane] = B;
        bS[2 * lane + 1] = C;
        if (lane == 31) bS[64] = F;
        if (lane == 0)  kB_sh = kB;
    }

    // join fwd/bwd warps
    asm volatile("bar.sync 1, 64;" ::: "memory");
    if (wid != 0) return;

    // P_stored = sum_s alpha_127(s) * beta_127(s)   (times 2^-(kF+kB))
    float term = b * bS[2 * lane] + c * bS[2 * lane + 1];
    if (lane == 31) term += f * bS[64];
    #pragma unroll
    for (int off = 16; off; off >>= 1)
        term += __shfl_xor_sync(WMASK, term, off);

    int win = 0;
    if (lane == 0) {
        float ll2 = __log2f(term) - (float)(kF + kB_sh);
        g_nll[n] = -(ll2 * LN2) / (float)S_;
        __threadfence();                  // release g_nll
        int old = atomicAdd(&g_done, 1);
        win = (old == N_ - 1);
    }
    win = __shfl_sync(WMASK, win, 0);
    if (win) {                            // last finisher computes the mean
        __threadfence();                  // acquire all g_nll
        float v = __ldcg(&g_nll[lane]) + __ldcg(&g_nll[lane + 32]);
        #pragma unroll
        for (int off = 16; off; off >>= 1)
            v += __shfl_xor_sync(WMASK, v, off);
        if (lane == 0) { out[0] = v / (float)N_; g_done = 0; }
    }
}

extern "C" void kernel_launch(void* const* d_in, const int* in_sizes, int n_in,
                              void* d_out, int out_size) {
    const float* y_pred   = (const float*)d_in[0];
    const int*   y_target = (const int*)d_in[1];

    k_softmax_gather<<<PG1, 512>>>(y_pred, y_target);

    cudaFuncSetAttribute(k_ctc_dp, cudaFuncAttributeMaxDynamicSharedMemorySize,
                         TILE_F * (int)sizeof(float));

    // Programmatic dependent launch: pre-stage k2 so its CTAs occupy SMs the
    // moment k1 drains; griddepcontrol.wait inside k2 provides the ordering.
    cudaLaunchConfig_t cfg = {};
    cfg.gridDim  = dim3(N_);
    cfg.blockDim = dim3(128);
    cfg.dynamicSmemBytes = TILE_F * sizeof(float);
    cfg.stream = 0;                       // same (legacy) stream as k1
    cudaLaunchAttribute attr[1];
    attr[0].id = cudaLaunchAttributeProgrammaticStreamSerialization;
    attr[0].val.programmaticStreamSerializationAllowed = 1;
    cfg.attrs = attr;
    cfg.numAttrs = 1;
    cudaLaunchKernelEx(&cfg, k_ctc_dp, y_target, (float*)d_out);
}